// round 13
// baseline (speedup 1.0000x reference)
#include <cuda_runtime.h>
#include <cuda_fp16.h>
#include <cstdint>

#define BB 32
#define SS 512
#define DD 768
#define OO 768
#define EE 8
#define SCH 8                      // pool s-chunks

// fp16 GEMM tiling
#define BM 128
#define BN 128
#define BKH 64                     // 64 halfs = 128B rows
#define KCHH (DD / BKH)            // 12 k-chunks
#define LDAH 72                    // padded row stride (halfs) -> conflict-free ldmatrix
#define BUFSZH (128 * LDAH)        // halfs per tile buffer

// ---------------- scratch (device globals; no allocation allowed) ----------
__device__ float  g_pool_part[SCH * BB * DD];
__device__ float  g_gate_val[BB * 2];
__device__ int    g_gate_idx[BB * 2];
__device__ __half g_xh[(size_t)BB * SS * DD];   // 25.2MB fp16 copy of x
__device__ __half g_wh[(size_t)EE * OO * DD];   // 9.4MB fp16 experts (L2-resident)
__device__ float  g_bias_c[BB * OO];

// ---------------- kernel 1: partial pooled sums + fp16 conversion of x -------
__global__ void smoe_pool_kernel(const float* __restrict__ x) {
    const int b = blockIdx.x;
    const int sc = blockIdx.y;
    const int d = blockIdx.z * 256 + threadIdx.x;
    const size_t base = (size_t)b * SS * DD + (size_t)sc * (SS / SCH) * DD + d;
    const float* xp = x + base;
    __half* xh = g_xh + base;
    float sum = 0.f;
#pragma unroll 8
    for (int i = 0; i < SS / SCH; i++) {
        float v = xp[(size_t)i * DD];
        sum += v;
        xh[(size_t)i * DD] = __float2half_rn(v);
    }
    g_pool_part[(sc * BB + b) * DD + d] = sum;
}

// ---------------- kernel 1.5: convert 8 expert weight mats to fp16 -----------
// 8*768*768 = 4.72M elems; thread handles 8 (two float4 -> one uint4 of halfs)
__global__ __launch_bounds__(256)
void smoe_convert_kernel(const float* __restrict__ weight) {
    const size_t i = (size_t)blockIdx.x * 256 + threadIdx.x;   // uint4-of-8-halfs idx
    const float4* w4 = (const float4*)weight;
    float4 a = w4[2 * i], b = w4[2 * i + 1];
    __half2 h0 = __floats2half2_rn(a.x, a.y);
    __half2 h1 = __floats2half2_rn(a.z, a.w);
    __half2 h2 = __floats2half2_rn(b.x, b.y);
    __half2 h3 = __floats2half2_rn(b.z, b.w);
    uint4 r;
    r.x = *(uint32_t*)&h0; r.y = *(uint32_t*)&h1;
    r.z = *(uint32_t*)&h2; r.w = *(uint32_t*)&h3;
    ((uint4*)g_wh)[i] = r;
}

// ---------------- kernel 2: gating + top-2 + aux loss + bias combine ---------
__device__ __forceinline__ float cv_squared8(const float* v) {
    float m = 0.f;
#pragma unroll
    for (int e = 0; e < EE; e++) m += v[e];
    m *= (1.0f / EE);
    float var = 0.f;
#pragma unroll
    for (int e = 0; e < EE; e++) { float dv = v[e] - m; var += dv * dv; }
    var *= (1.0f / (EE - 1));
    return var / (m * m + 1e-10f);
}

__global__ void smoe_gate_kernel(const float* __restrict__ w_gate,
                                 const float* __restrict__ bias,
                                 float* __restrict__ loss_out) {
    __shared__ float s_wg[DD * EE];          // 24 KB
    __shared__ float s_logits[BB][EE];
    __shared__ float s_gates[BB][EE];
    __shared__ float s_gv[BB][2];
    __shared__ int   s_gi[BB][2];

    const int tid = threadIdx.x;             // 256 threads
    const int lane = tid & 31;
    const int warp = tid >> 5;               // 8 warps; warp owns 4 batches

    for (int i = tid; i < DD * EE; i += 256) s_wg[i] = w_gate[i];
    __syncthreads();

#pragma unroll
    for (int bi = 0; bi < 4; bi++) {
        const int b = warp * 4 + bi;
        float le[EE];
#pragma unroll
        for (int e = 0; e < EE; e++) le[e] = 0.f;

        for (int d = lane; d < DD; d += 32) {
            float pv = 0.f;
#pragma unroll
            for (int s = 0; s < SCH; s++) pv += g_pool_part[(s * BB + b) * DD + d];
            pv *= (1.0f / SS);
#pragma unroll
            for (int e = 0; e < EE; e++) le[e] += pv * s_wg[d * EE + e];
        }
#pragma unroll
        for (int e = 0; e < EE; e++) {
#pragma unroll
            for (int off = 16; off; off >>= 1)
                le[e] += __shfl_xor_sync(0xffffffffu, le[e], off);
        }
        if (lane < EE) s_logits[b][lane] = le[lane];
    }
    __syncthreads();

    if (tid < BB) {
        const int b = tid;
        float logits[EE];
#pragma unroll
        for (int e = 0; e < EE; e++) logits[e] = s_logits[b][e];

        int i1 = 0; float v1 = logits[0];
#pragma unroll
        for (int e = 1; e < EE; e++) if (logits[e] > v1) { v1 = logits[e]; i1 = e; }
        int i2 = -1; float v2 = -1e30f;
#pragma unroll
        for (int e = 0; e < EE; e++)
            if (e != i1 && logits[e] > v2) { v2 = logits[e]; i2 = e; }

        float ex = expf(v2 - v1);
        float inv = 1.0f / (1.0f + ex);
        float gtop = inv, gsec = ex * inv;

#pragma unroll
        for (int e = 0; e < EE; e++) s_gates[b][e] = 0.f;
        s_gates[b][i1] = gtop;
        s_gates[b][i2] = gsec;
        s_gv[b][0] = gtop; s_gv[b][1] = gsec;
        s_gi[b][0] = i1;   s_gi[b][1] = i2;

        g_gate_idx[b * 2 + 0] = i1;
        g_gate_idx[b * 2 + 1] = i2;
        g_gate_val[b * 2 + 0] = gtop;
        g_gate_val[b * 2 + 1] = gsec;
    }
    __syncthreads();

    // combined bias: g_bias_c[b][n] = g0*bias[e0][n] + g1*bias[e1][n]
    for (int i = tid; i < BB * OO; i += 256) {
        int b = i / OO, n = i - b * OO;
        g_bias_c[i] = s_gv[b][0] * bias[s_gi[b][0] * OO + n]
                    + s_gv[b][1] * bias[s_gi[b][1] * OO + n];
    }

    if (tid == 0) {
        float imp[EE], ldv[EE];
#pragma unroll
        for (int e = 0; e < EE; e++) {
            float s = 0.f, c = 0.f;
            for (int bi = 0; bi < BB; bi++) {
                float g = s_gates[bi][e];
                s += g;
                if (g > 0.f) c += 1.f;
            }
            imp[e] = s; ldv[e] = c;
        }
        loss_out[0] = (cv_squared8(imp) + cv_squared8(ldv)) * 0.01f;
    }
}

// ---------------- kernel 3: FP16 GEMM with in-CTA expert combine -------------
__device__ __forceinline__ uint32_t smem_u32(const void* p) {
    return (uint32_t)__cvta_generic_to_shared(p);
}

__device__ __forceinline__ void ldsm_x4(uint32_t (&r)[4], uint32_t addr) {
    asm volatile("ldmatrix.sync.aligned.m8n8.x4.shared.b16 {%0,%1,%2,%3}, [%4];"
                 : "=r"(r[0]), "=r"(r[1]), "=r"(r[2]), "=r"(r[3]) : "r"(addr));
}

__device__ __forceinline__ void mma_f16(float (&d)[4], const uint32_t (&a)[4],
                                        uint32_t b0, uint32_t b1) {
    asm volatile(
        "mma.sync.aligned.m16n8k16.row.col.f32.f16.f16.f32 "
        "{%0,%1,%2,%3}, {%4,%5,%6,%7}, {%8,%9}, {%0,%1,%2,%3};"
        : "+f"(d[0]), "+f"(d[1]), "+f"(d[2]), "+f"(d[3])
        : "r"(a[0]), "r"(a[1]), "r"(a[2]), "r"(a[3]), "r"(b0), "r"(b1));
}

__device__ __forceinline__ void cp_async16(uint32_t dst, const void* src) {
    asm volatile("cp.async.ca.shared.global [%0], [%1], 16;" :: "r"(dst), "l"(src));
}

__device__ __forceinline__ uint32_t comb2(uint32_t w0, uint32_t w1,
                                          float g0, float g1) {
    __half2 h0 = *reinterpret_cast<__half2*>(&w0);
    __half2 h1 = *reinterpret_cast<__half2*>(&w1);
    float2 f0 = __half22float2(h0);
    float2 f1 = __half22float2(h1);
    __half2 r = __floats2half2_rn(g0 * f0.x + g1 * f1.x,
                                  g0 * f0.y + g1 * f1.y);
    return *reinterpret_cast<uint32_t*>(&r);
}

__global__ __launch_bounds__(256, 2)
void smoe_gemm_f16(float* __restrict__ out) {
    extern __shared__ __half smh[];
    __half* As = smh;                   // [2][BUFSZH]
    __half* Bc = smh + 2 * BUFSZH;      // [2][BUFSZH] combined B tiles

    const int b = blockIdx.z;
    const int e0 = g_gate_idx[2 * b], e1 = g_gate_idx[2 * b + 1];
    const float g0 = g_gate_val[2 * b], g1 = g_gate_val[2 * b + 1];
    const int nBlk = blockIdx.x * BN;
    const int mBlk = blockIdx.y * BM;

    const int tid = threadIdx.x;
    const int lane = tid & 31;
    const int wid = tid >> 5;
    const int warpM = wid >> 2;      // 0..1 -> 64-row slab
    const int warpN = wid & 3;       // 0..3 -> 32-col slab

    const __half* gA  = g_xh + (size_t)b  * SS * DD + (size_t)mBlk * DD;
    const __half* gW0 = g_wh + (size_t)e0 * OO * DD + (size_t)nBlk * DD;
    const __half* gW1 = g_wh + (size_t)e1 * OO * DD + (size_t)nBlk * DD;

    const int aRow = (lane & 7) + ((lane >> 3) & 1) * 8;
    const int aK   = ((lane >> 4) & 1) * 8;
    int aOff[4];
#pragma unroll
    for (int mf = 0; mf < 4; mf++)
        aOff[mf] = (warpM * 64 + mf * 16 + aRow) * LDAH + aK;

    const int bRow = (lane & 7) + ((lane >> 4) & 1) * 8;
    const int bK   = ((lane >> 3) & 1) * 8;
    int bOff[2];
#pragma unroll
    for (int p = 0; p < 2; p++)
        bOff[p] = (warpN * 32 + p * 16 + bRow) * LDAH + bK;

    float acc[4][4][4];
#pragma unroll
    for (int i = 0; i < 4; i++)
#pragma unroll
        for (int j = 0; j < 4; j++)
#pragma unroll
            for (int k = 0; k < 4; k++) acc[i][j][k] = 0.f;

    // A-only cp.async loader: 128x64 halfs (16KB)
    auto issueA = [&](int chunk, int buf) {
        const int kt = chunk * BKH;
#pragma unroll
        for (int p = 0; p < 4; p++) {
            int c = tid + p * 256;
            int row = c >> 3;
            int q8 = (c & 7) * 8;
            cp_async16(smem_u32(As + buf * BUFSZH + row * LDAH + q8),
                       gA + (size_t)row * DD + kt + q8);
        }
        asm volatile("cp.async.commit_group;");
    };

    issueA(0, 0);

#pragma unroll 1
    for (int c = 0; c < KCHH; c++) {
        const int buf = c & 1;
        if (c + 1 < KCHH) issueA(c + 1, buf ^ 1);

        // build combined B tile for chunk c (Bc[buf] free since compute c-2)
        {
            const int kt = c * BKH;
#pragma unroll
            for (int p = 0; p < 4; p += 2) {
                uint4 w0a, w1a, w0b, w1b;
                int ua = tid + p * 256, ub = tid + (p + 1) * 256;
                int ra = ua >> 3, qa = (ua & 7) * 8;
                int rb = ub >> 3, qb = (ub & 7) * 8;
                w0a = *(const uint4*)(gW0 + (size_t)ra * DD + kt + qa);
                w1a = *(const uint4*)(gW1 + (size_t)ra * DD + kt + qa);
                w0b = *(const uint4*)(gW0 + (size_t)rb * DD + kt + qb);
                w1b = *(const uint4*)(gW1 + (size_t)rb * DD + kt + qb);
                uint4 ca, cb;
                ca.x = comb2(w0a.x, w1a.x, g0, g1);
                ca.y = comb2(w0a.y, w1a.y, g0, g1);
                ca.z = comb2(w0a.z, w1a.z, g0, g1);
                ca.w = comb2(w0a.w, w1a.w, g0, g1);
                cb.x = comb2(w0b.x, w1b.x, g0, g1);
                cb.y = comb2(w0b.y, w1b.y, g0, g1);
                cb.z = comb2(w0b.z, w1b.z, g0, g1);
                cb.w = comb2(w0b.w, w1b.w, g0, g1);
                *(uint4*)(Bc + buf * BUFSZH + ra * LDAH + qa) = ca;
                *(uint4*)(Bc + buf * BUFSZH + rb * LDAH + qb) = cb;
            }
        }

        if (c + 1 < KCHH) { asm volatile("cp.async.wait_group 1;"); }
        else              { asm volatile("cp.async.wait_group 0;"); }
        __syncthreads();                       // As[buf] + Bc[buf] visible

        const int bo = buf * BUFSZH;
#pragma unroll
        for (int kk = 0; kk < BKH; kk += 16) {
            uint32_t a[4][4];
#pragma unroll
            for (int mf = 0; mf < 4; mf++)
                ldsm_x4(a[mf], smem_u32(As + bo + aOff[mf] + kk));

#pragma unroll
            for (int p = 0; p < 2; p++) {
                uint32_t w[4];
                ldsm_x4(w, smem_u32(Bc + bo + bOff[p] + kk));
#pragma unroll
                for (int mf = 0; mf < 4; mf++) {
                    mma_f16(acc[mf][2 * p + 0], a[mf], w[0], w[1]);
                    mma_f16(acc[mf][2 * p + 1], a[mf], w[2], w[3]);
                }
            }
        }
        __syncthreads();                       // compute done before reuse
    }

    // --- epilogue: combined bias + float2 stores ----------------------------
    float2 bb[4];
#pragma unroll
    for (int nf = 0; nf < 4; nf++) {
        int n = nBlk + warpN * 32 + nf * 8 + (lane & 3) * 2;
        bb[nf].x = g_bias_c[b * OO + n];
        bb[nf].y = g_bias_c[b * OO + n + 1];
    }

    float* C = out + (size_t)b * SS * OO;
#pragma unroll
    for (int mf = 0; mf < 4; mf++) {
        int m = mBlk + warpM * 64 + mf * 16 + (lane >> 2);
#pragma unroll
        for (int nf = 0; nf < 4; nf++) {
            int n = nBlk + warpN * 32 + nf * 8 + (lane & 3) * 2;
            float2 v0, v1;
            v0.x = acc[mf][nf][0] + bb[nf].x;
            v0.y = acc[mf][nf][1] + bb[nf].y;
            v1.x = acc[mf][nf][2] + bb[nf].x;
            v1.y = acc[mf][nf][3] + bb[nf].y;
            *(float2*)(C + (size_t)m * OO + n) = v0;
            *(float2*)(C + (size_t)(m + 8) * OO + n) = v1;
        }
    }
}

// ---------------- launch ------------------------------------------------------
extern "C" void kernel_launch(void* const* d_in, const int* in_sizes, int n_in,
                              void* d_out, int out_size) {
    const float* x      = (const float*)d_in[0];  // (32,512,768)
    const float* w_gate = (const float*)d_in[1];  // (768,8)
    const float* weight = (const float*)d_in[2];  // (8,768,768)
    const float* bias   = (const float*)d_in[3];  // (8,768)
    float* out = (float*)d_out;
    float* loss_out = out + (out_size - 1);

    const int smem_bytes = 4 * BUFSZH * 2;  // 73728 B (A + combined-B, double-buffered)
    cudaFuncSetAttribute(smoe_gemm_f16,
                         cudaFuncAttributeMaxDynamicSharedMemorySize, smem_bytes);

    smoe_pool_kernel<<<dim3(BB, SCH, DD / 256), 256>>>(x);
    smoe_convert_kernel<<<EE * OO * DD / (256 * 8), 256>>>(weight);
    smoe_gate_kernel<<<1, 256>>>(w_gate, bias, loss_out);
    smoe_gemm_f16<<<dim3(OO / BN, SS / BM, BB), 256, smem_bytes>>>(out);
}

// round 14
// speedup vs baseline: 1.0421x; 1.0421x over previous
#include <cuda_runtime.h>
#include <cuda_fp16.h>
#include <cstdint>

#define BB 32
#define SS 512
#define DD 768
#define OO 768
#define EE 8
#define SCH 8                      // pool s-chunks

// fp16 GEMM tiling
#define BM 128
#define BN 128
#define BKH 64                     // 64 halfs = 128B rows
#define KCHH (DD / BKH)            // 12 k-chunks
#define LDAH 72                    // padded row stride (halfs) -> conflict-free ldmatrix
#define BUFSZH (128 * LDAH)        // halfs per tile buffer

// ---------------- scratch (device globals; no allocation allowed) ----------
__device__ float  g_pool_part[SCH * BB * DD];
__device__ float  g_gate_val[BB * 2];
__device__ int    g_gate_idx[BB * 2];
__device__ __half g_xh[(size_t)BB * SS * DD];   // 25.2MB fp16 copy of x
__device__ __half g_wch[(size_t)BB * OO * DD];  // 37.7MB combined expert weights (fp16)
__device__ float  g_bias_c[BB * OO];

// ---------------- kernel 1: partial pooled sums + fp16 conversion of x -------
__global__ void smoe_pool_kernel(const float* __restrict__ x) {
    const int b = blockIdx.x;
    const int sc = blockIdx.y;
    const int d = blockIdx.z * 256 + threadIdx.x;
    const size_t base = (size_t)b * SS * DD + (size_t)sc * (SS / SCH) * DD + d;
    const float* xp = x + base;
    __half* xh = g_xh + base;
    float sum = 0.f;
#pragma unroll 8
    for (int i = 0; i < SS / SCH; i++) {
        float v = xp[(size_t)i * DD];
        sum += v;
        xh[(size_t)i * DD] = __float2half_rn(v);
    }
    g_pool_part[(sc * BB + b) * DD + d] = sum;
}

// ---------------- kernel 2: gating + top-2 + aux loss + bias combine ---------
__device__ __forceinline__ float cv_squared8(const float* v) {
    float m = 0.f;
#pragma unroll
    for (int e = 0; e < EE; e++) m += v[e];
    m *= (1.0f / EE);
    float var = 0.f;
#pragma unroll
    for (int e = 0; e < EE; e++) { float dv = v[e] - m; var += dv * dv; }
    var *= (1.0f / (EE - 1));
    return var / (m * m + 1e-10f);
}

__global__ void smoe_gate_kernel(const float* __restrict__ w_gate,
                                 const float* __restrict__ bias,
                                 float* __restrict__ loss_out) {
    __shared__ float s_wg[DD * EE];          // 24 KB
    __shared__ float s_logits[BB][EE];
    __shared__ float s_gates[BB][EE];
    __shared__ float s_gv[BB][2];
    __shared__ int   s_gi[BB][2];

    const int tid = threadIdx.x;             // 256 threads
    const int lane = tid & 31;
    const int warp = tid >> 5;               // 8 warps; warp owns 4 batches

    for (int i = tid; i < DD * EE; i += 256) s_wg[i] = w_gate[i];
    __syncthreads();

#pragma unroll
    for (int bi = 0; bi < 4; bi++) {
        const int b = warp * 4 + bi;
        float le[EE];
#pragma unroll
        for (int e = 0; e < EE; e++) le[e] = 0.f;

        for (int d = lane; d < DD; d += 32) {
            float pv = 0.f;
#pragma unroll
            for (int s = 0; s < SCH; s++) pv += g_pool_part[(s * BB + b) * DD + d];
            pv *= (1.0f / SS);
#pragma unroll
            for (int e = 0; e < EE; e++) le[e] += pv * s_wg[d * EE + e];
        }
#pragma unroll
        for (int e = 0; e < EE; e++) {
#pragma unroll
            for (int off = 16; off; off >>= 1)
                le[e] += __shfl_xor_sync(0xffffffffu, le[e], off);
        }
        if (lane < EE) s_logits[b][lane] = le[lane];
    }
    __syncthreads();

    if (tid < BB) {
        const int b = tid;
        float logits[EE];
#pragma unroll
        for (int e = 0; e < EE; e++) logits[e] = s_logits[b][e];

        int i1 = 0; float v1 = logits[0];
#pragma unroll
        for (int e = 1; e < EE; e++) if (logits[e] > v1) { v1 = logits[e]; i1 = e; }
        int i2 = -1; float v2 = -1e30f;
#pragma unroll
        for (int e = 0; e < EE; e++)
            if (e != i1 && logits[e] > v2) { v2 = logits[e]; i2 = e; }

        float ex = expf(v2 - v1);
        float inv = 1.0f / (1.0f + ex);
        float gtop = inv, gsec = ex * inv;

#pragma unroll
        for (int e = 0; e < EE; e++) s_gates[b][e] = 0.f;
        s_gates[b][i1] = gtop;
        s_gates[b][i2] = gsec;
        s_gv[b][0] = gtop; s_gv[b][1] = gsec;
        s_gi[b][0] = i1;   s_gi[b][1] = i2;

        g_gate_idx[b * 2 + 0] = i1;
        g_gate_idx[b * 2 + 1] = i2;
        g_gate_val[b * 2 + 0] = gtop;
        g_gate_val[b * 2 + 1] = gsec;
    }
    __syncthreads();

    // combined bias: g_bias_c[b][n] = g0*bias[e0][n] + g1*bias[e1][n]
    for (int i = tid; i < BB * OO; i += 256) {
        int b = i / OO, n = i - b * OO;
        g_bias_c[i] = s_gv[b][0] * bias[s_gi[b][0] * OO + n]
                    + s_gv[b][1] * bias[s_gi[b][1] * OO + n];
    }

    if (tid == 0) {
        float imp[EE], ldv[EE];
#pragma unroll
        for (int e = 0; e < EE; e++) {
            float s = 0.f, c = 0.f;
            for (int bi = 0; bi < BB; bi++) {
                float g = s_gates[bi][e];
                s += g;
                if (g > 0.f) c += 1.f;
            }
            imp[e] = s; ldv[e] = c;
        }
        loss_out[0] = (cv_squared8(imp) + cv_squared8(ldv)) * 0.01f;
    }
}

// ---------------- kernel 2.5: combine v2 — read experts ONCE -----------------
// Thread owns one 8-float chunk; loads it from all 8 experts (64 floats),
// then emits all 32 per-batch fp16 combinations from registers.
// Traffic: 18.9MB read + 37.7MB write (vs 151MB read before).
__global__ __launch_bounds__(256)
void smoe_combine_kernel(const float* __restrict__ weight) {
    __shared__ float s_g[BB][2];
    __shared__ int   s_e[BB][2];
    if (threadIdx.x < BB) {
        s_g[threadIdx.x][0] = g_gate_val[2 * threadIdx.x];
        s_g[threadIdx.x][1] = g_gate_val[2 * threadIdx.x + 1];
        s_e[threadIdx.x][0] = g_gate_idx[2 * threadIdx.x];
        s_e[threadIdx.x][1] = g_gate_idx[2 * threadIdx.x + 1];
    }
    __syncthreads();

    const size_t i = (size_t)blockIdx.x * 256 + threadIdx.x; // 8-elem chunk id
    const size_t nchunks = (size_t)OO * DD / 8;              // 73728
    if (i >= nchunks) return;

    const float4* w4 = (const float4*)weight;
    float4 w[EE][2];
#pragma unroll
    for (int e = 0; e < EE; e++) {
        size_t base = (size_t)e * OO * DD / 4 + 2 * i;
        w[e][0] = w4[base];
        w[e][1] = w4[base + 1];
    }

#pragma unroll 4
    for (int b = 0; b < BB; b++) {
        const float g0 = s_g[b][0], g1 = s_g[b][1];
        const int e0 = s_e[b][0], e1 = s_e[b][1];
        float4 a0 = w[e0][0], a1 = w[e0][1];
        float4 c0 = w[e1][0], c1 = w[e1][1];
        __half2 h0 = __floats2half2_rn(g0 * a0.x + g1 * c0.x, g0 * a0.y + g1 * c0.y);
        __half2 h1 = __floats2half2_rn(g0 * a0.z + g1 * c0.z, g0 * a0.w + g1 * c0.w);
        __half2 h2 = __floats2half2_rn(g0 * a1.x + g1 * c1.x, g0 * a1.y + g1 * c1.y);
        __half2 h3 = __floats2half2_rn(g0 * a1.z + g1 * c1.z, g0 * a1.w + g1 * c1.w);
        uint4 r;
        r.x = *(uint32_t*)&h0; r.y = *(uint32_t*)&h1;
        r.z = *(uint32_t*)&h2; r.w = *(uint32_t*)&h3;
        *(uint4*)(g_wch + (size_t)b * OO * DD + i * 8) = r;
    }
}

// ---------------- kernel 3: FP16 mma.sync GEMM (2-operand, measured 66.6us) --
__device__ __forceinline__ uint32_t smem_u32(const void* p) {
    return (uint32_t)__cvta_generic_to_shared(p);
}

__device__ __forceinline__ void ldsm_x4(uint32_t (&r)[4], uint32_t addr) {
    asm volatile("ldmatrix.sync.aligned.m8n8.x4.shared.b16 {%0,%1,%2,%3}, [%4];"
                 : "=r"(r[0]), "=r"(r[1]), "=r"(r[2]), "=r"(r[3]) : "r"(addr));
}

__device__ __forceinline__ void mma_f16(float (&d)[4], const uint32_t (&a)[4],
                                        uint32_t b0, uint32_t b1) {
    asm volatile(
        "mma.sync.aligned.m16n8k16.row.col.f32.f16.f16.f32 "
        "{%0,%1,%2,%3}, {%4,%5,%6,%7}, {%8,%9}, {%0,%1,%2,%3};"
        : "+f"(d[0]), "+f"(d[1]), "+f"(d[2]), "+f"(d[3])
        : "r"(a[0]), "r"(a[1]), "r"(a[2]), "r"(a[3]), "r"(b0), "r"(b1));
}

__device__ __forceinline__ void cp_async16(uint32_t dst, const void* src) {
    asm volatile("cp.async.ca.shared.global [%0], [%1], 16;" :: "r"(dst), "l"(src));
}

__global__ __launch_bounds__(256, 2)
void smoe_gemm_f16(float* __restrict__ out) {
    extern __shared__ __half smh[];
    __half* As = smh;                   // [2][BUFSZH]
    __half* Bs = smh + 2 * BUFSZH;      // [2][BUFSZH]

    const int b = blockIdx.z;
    const int nBlk = blockIdx.x * BN;
    const int mBlk = blockIdx.y * BM;

    const int tid = threadIdx.x;
    const int lane = tid & 31;
    const int wid = tid >> 5;
    const int warpM = wid >> 2;      // 0..1 -> 64-row slab
    const int warpN = wid & 3;       // 0..3 -> 32-col slab

    const __half* gA = g_xh  + (size_t)b * SS * DD + (size_t)mBlk * DD;
    const __half* gB = g_wch + (size_t)b * OO * DD + (size_t)nBlk * DD;

    const int aRow = (lane & 7) + ((lane >> 3) & 1) * 8;
    const int aK   = ((lane >> 4) & 1) * 8;
    int aOff[4];
#pragma unroll
    for (int mf = 0; mf < 4; mf++)
        aOff[mf] = (warpM * 64 + mf * 16 + aRow) * LDAH + aK;

    const int bRow = (lane & 7) + ((lane >> 4) & 1) * 8;
    const int bK   = ((lane >> 3) & 1) * 8;
    int bOff[2];
#pragma unroll
    for (int p = 0; p < 2; p++)
        bOff[p] = (warpN * 32 + p * 16 + bRow) * LDAH + bK;

    float acc[4][4][4];
#pragma unroll
    for (int i = 0; i < 4; i++)
#pragma unroll
        for (int j = 0; j < 4; j++)
#pragma unroll
            for (int k = 0; k < 4; k++) acc[i][j][k] = 0.f;

    auto issue = [&](int chunk, int buf) {
        const int kt = chunk * BKH;
#pragma unroll
        for (int p = 0; p < 4; p++) {
            int c = tid + p * 256;
            int row = c >> 3;
            int q8 = (c & 7) * 8;
            int so = buf * BUFSZH + row * LDAH + q8;
            size_t go = (size_t)row * DD + kt + q8;
            cp_async16(smem_u32(As + so), gA + go);
            cp_async16(smem_u32(Bs + so), gB + go);
        }
        asm volatile("cp.async.commit_group;");
    };

    issue(0, 0);

#pragma unroll 1
    for (int c = 0; c < KCHH; c++) {
        const int buf = c & 1;
        if (c + 1 < KCHH) {
            issue(c + 1, buf ^ 1);
            asm volatile("cp.async.wait_group 1;");
        } else {
            asm volatile("cp.async.wait_group 0;");
        }
        __syncthreads();

        const int bo = buf * BUFSZH;
#pragma unroll
        for (int kk = 0; kk < BKH; kk += 16) {
            uint32_t a[4][4];
#pragma unroll
            for (int mf = 0; mf < 4; mf++)
                ldsm_x4(a[mf], smem_u32(As + bo + aOff[mf] + kk));

#pragma unroll
            for (int p = 0; p < 2; p++) {
                uint32_t w[4];
                ldsm_x4(w, smem_u32(Bs + bo + bOff[p] + kk));
#pragma unroll
                for (int mf = 0; mf < 4; mf++) {
                    mma_f16(acc[mf][2 * p + 0], a[mf], w[0], w[1]);
                    mma_f16(acc[mf][2 * p + 1], a[mf], w[2], w[3]);
                }
            }
        }
        __syncthreads();
    }

    float2 bb[4];
#pragma unroll
    for (int nf = 0; nf < 4; nf++) {
        int n = nBlk + warpN * 32 + nf * 8 + (lane & 3) * 2;
        bb[nf].x = g_bias_c[b * OO + n];
        bb[nf].y = g_bias_c[b * OO + n + 1];
    }

    float* C = out + (size_t)b * SS * OO;
#pragma unroll
    for (int mf = 0; mf < 4; mf++) {
        int m = mBlk + warpM * 64 + mf * 16 + (lane >> 2);
#pragma unroll
        for (int nf = 0; nf < 4; nf++) {
            int n = nBlk + warpN * 32 + nf * 8 + (lane & 3) * 2;
            float2 v0, v1;
            v0.x = acc[mf][nf][0] + bb[nf].x;
            v0.y = acc[mf][nf][1] + bb[nf].y;
            v1.x = acc[mf][nf][2] + bb[nf].x;
            v1.y = acc[mf][nf][3] + bb[nf].y;
            *(float2*)(C + (size_t)m * OO + n) = v0;
            *(float2*)(C + (size_t)(m + 8) * OO + n) = v1;
        }
    }
}

// ---------------- launch ------------------------------------------------------
extern "C" void kernel_launch(void* const* d_in, const int* in_sizes, int n_in,
                              void* d_out, int out_size) {
    const float* x      = (const float*)d_in[0];  // (32,512,768)
    const float* w_gate = (const float*)d_in[1];  // (768,8)
    const float* weight = (const float*)d_in[2];  // (8,768,768)
    const float* bias   = (const float*)d_in[3];  // (8,768)
    float* out = (float*)d_out;
    float* loss_out = out + (out_size - 1);

    const int smem_bytes = 4 * BUFSZH * 2;  // 73728 B (A/B double-buffered, fp16)
    cudaFuncSetAttribute(smoe_gemm_f16,
                         cudaFuncAttributeMaxDynamicSharedMemorySize, smem_bytes);

    smoe_pool_kernel<<<dim3(BB, SCH, DD / 256), 256>>>(x);
    smoe_gate_kernel<<<1, 256>>>(w_gate, bias, loss_out);
    smoe_combine_kernel<<<(OO * DD / 8 + 255) / 256, 256>>>(weight);
    smoe_gemm_f16<<<dim3(OO / BN, SS / BM, BB), 256, smem_bytes>>>(out);
}

// round 15
// speedup vs baseline: 1.0646x; 1.0217x over previous
#include <cuda_runtime.h>
#include <cuda_fp16.h>
#include <cstdint>

#define BB 32
#define SS 512
#define DD 768
#define OO 768
#define EE 8
#define SCH 8                      // pool s-chunks

// fp16 GEMM tiling
#define BM 128
#define BN 128
#define BKH 64                     // 64 halfs = 128B rows
#define KCHH (DD / BKH)            // 12 k-chunks
#define LDAH 72                    // padded row stride (halfs) -> conflict-free ldmatrix
#define BUFSZH (128 * LDAH)        // halfs per tile buffer

// ---------------- scratch (device globals; no allocation allowed) ----------
__device__ float  g_pool_part[SCH * BB * DD];
__device__ float  g_gate_val[BB * 2];
__device__ int    g_gate_idx[BB * 2];
__device__ __half g_xh[(size_t)BB * SS * DD];   // 25.2MB fp16 copy of x
__device__ __half g_wch[(size_t)BB * OO * DD];  // 37.7MB combined expert weights (fp16)
__device__ float  g_bias_c[BB * OO];

// ---------------- kernel 1: partial pooled sums + fp16 conversion of x -------
__global__ void smoe_pool_kernel(const float* __restrict__ x) {
    const int b = blockIdx.x;
    const int sc = blockIdx.y;
    const int d = blockIdx.z * 256 + threadIdx.x;
    const size_t base = (size_t)b * SS * DD + (size_t)sc * (SS / SCH) * DD + d;
    const float* xp = x + base;
    __half* xh = g_xh + base;
    float sum = 0.f;
#pragma unroll 8
    for (int i = 0; i < SS / SCH; i++) {
        float v = xp[(size_t)i * DD];
        sum += v;
        xh[(size_t)i * DD] = __float2half_rn(v);
    }
    g_pool_part[(sc * BB + b) * DD + d] = sum;
}

// ---------------- kernel 2: gating + top-2 + aux loss + bias combine ---------
__device__ __forceinline__ float cv_squared8(const float* v) {
    float m = 0.f;
#pragma unroll
    for (int e = 0; e < EE; e++) m += v[e];
    m *= (1.0f / EE);
    float var = 0.f;
#pragma unroll
    for (int e = 0; e < EE; e++) { float dv = v[e] - m; var += dv * dv; }
    var *= (1.0f / (EE - 1));
    return var / (m * m + 1e-10f);
}

__global__ void smoe_gate_kernel(const float* __restrict__ w_gate,
                                 const float* __restrict__ bias,
                                 float* __restrict__ loss_out) {
    __shared__ float s_wg[DD * EE];          // 24 KB
    __shared__ float s_logits[BB][EE];
    __shared__ float s_gates[BB][EE];
    __shared__ float s_gv[BB][2];
    __shared__ int   s_gi[BB][2];

    const int tid = threadIdx.x;             // 256 threads
    const int lane = tid & 31;
    const int warp = tid >> 5;               // 8 warps; warp owns 4 batches

    for (int i = tid; i < DD * EE; i += 256) s_wg[i] = w_gate[i];
    __syncthreads();

#pragma unroll
    for (int bi = 0; bi < 4; bi++) {
        const int b = warp * 4 + bi;
        float le[EE];
#pragma unroll
        for (int e = 0; e < EE; e++) le[e] = 0.f;

        for (int d = lane; d < DD; d += 32) {
            float pv = 0.f;
#pragma unroll
            for (int s = 0; s < SCH; s++) pv += g_pool_part[(s * BB + b) * DD + d];
            pv *= (1.0f / SS);
#pragma unroll
            for (int e = 0; e < EE; e++) le[e] += pv * s_wg[d * EE + e];
        }
#pragma unroll
        for (int e = 0; e < EE; e++) {
#pragma unroll
            for (int off = 16; off; off >>= 1)
                le[e] += __shfl_xor_sync(0xffffffffu, le[e], off);
        }
        if (lane < EE) s_logits[b][lane] = le[lane];
    }
    __syncthreads();

    if (tid < BB) {
        const int b = tid;
        float logits[EE];
#pragma unroll
        for (int e = 0; e < EE; e++) logits[e] = s_logits[b][e];

        int i1 = 0; float v1 = logits[0];
#pragma unroll
        for (int e = 1; e < EE; e++) if (logits[e] > v1) { v1 = logits[e]; i1 = e; }
        int i2 = -1; float v2 = -1e30f;
#pragma unroll
        for (int e = 0; e < EE; e++)
            if (e != i1 && logits[e] > v2) { v2 = logits[e]; i2 = e; }

        float ex = expf(v2 - v1);
        float inv = 1.0f / (1.0f + ex);
        float gtop = inv, gsec = ex * inv;

#pragma unroll
        for (int e = 0; e < EE; e++) s_gates[b][e] = 0.f;
        s_gates[b][i1] = gtop;
        s_gates[b][i2] = gsec;
        s_gv[b][0] = gtop; s_gv[b][1] = gsec;
        s_gi[b][0] = i1;   s_gi[b][1] = i2;

        g_gate_idx[b * 2 + 0] = i1;
        g_gate_idx[b * 2 + 1] = i2;
        g_gate_val[b * 2 + 0] = gtop;
        g_gate_val[b * 2 + 1] = gsec;
    }
    __syncthreads();

    // combined bias: g_bias_c[b][n] = g0*bias[e0][n] + g1*bias[e1][n]
    for (int i = tid; i < BB * OO; i += 256) {
        int b = i / OO, n = i - b * OO;
        g_bias_c[i] = s_gv[b][0] * bias[s_gi[b][0] * OO + n]
                    + s_gv[b][1] * bias[s_gi[b][1] * OO + n];
    }

    if (tid == 0) {
        float imp[EE], ldv[EE];
#pragma unroll
        for (int e = 0; e < EE; e++) {
            float s = 0.f, c = 0.f;
            for (int bi = 0; bi < BB; bi++) {
                float g = s_gates[bi][e];
                s += g;
                if (g > 0.f) c += 1.f;
            }
            imp[e] = s; ldv[e] = c;
        }
        loss_out[0] = (cv_squared8(imp) + cv_squared8(ldv)) * 0.01f;
    }
}

// ---------------- kernel 2.5: combine v3 — dense gates, compile-time indices -
// Thread owns one 8-float chunk; loads it from all 8 experts (registers,
// compile-time indexed), then for each batch accumulates sum_e g[b][e]*w[e]
// with a warp-uniform skip of zero gates. Reads experts ONCE (18.9MB),
// writes 37.7MB fp16.
__global__ __launch_bounds__(256)
void smoe_combine_kernel(const float* __restrict__ weight) {
    __shared__ float s_gd[BB][EE];           // dense gate matrix
    {
        const int t = threadIdx.x;           // 256 = BB*EE exactly
        s_gd[t >> 3][t & 7] = 0.f;
        __syncthreads();
        if (t < BB) {
            s_gd[t][g_gate_idx[2 * t + 0]] = g_gate_val[2 * t + 0];
            s_gd[t][g_gate_idx[2 * t + 1]] = g_gate_val[2 * t + 1];
        }
        __syncthreads();
    }

    const size_t i = (size_t)blockIdx.x * 256 + threadIdx.x; // 8-elem chunk id
    const float4* w4 = (const float4*)weight;

    float4 w[EE][2];                          // compile-time indexed only
#pragma unroll
    for (int e = 0; e < EE; e++) {
        size_t base = (size_t)e * (OO * DD / 4) + 2 * i;
        w[e][0] = w4[base];
        w[e][1] = w4[base + 1];
    }

#pragma unroll 4
    for (int b = 0; b < BB; b++) {
        float4 r0 = make_float4(0.f, 0.f, 0.f, 0.f);
        float4 r1 = make_float4(0.f, 0.f, 0.f, 0.f);
#pragma unroll
        for (int e = 0; e < EE; e++) {
            float g = s_gd[b][e];             // warp-uniform
            if (g != 0.f) {
                r0.x += g * w[e][0].x; r0.y += g * w[e][0].y;
                r0.z += g * w[e][0].z; r0.w += g * w[e][0].w;
                r1.x += g * w[e][1].x; r1.y += g * w[e][1].y;
                r1.z += g * w[e][1].z; r1.w += g * w[e][1].w;
            }
        }
        __half2 h0 = __floats2half2_rn(r0.x, r0.y);
        __half2 h1 = __floats2half2_rn(r0.z, r0.w);
        __half2 h2 = __floats2half2_rn(r1.x, r1.y);
        __half2 h3 = __floats2half2_rn(r1.z, r1.w);
        uint4 r;
        r.x = *(uint32_t*)&h0; r.y = *(uint32_t*)&h1;
        r.z = *(uint32_t*)&h2; r.w = *(uint32_t*)&h3;
        *(uint4*)(g_wch + (size_t)b * OO * DD + i * 8) = r;
    }
}

// ---------------- kernel 3: FP16 mma.sync GEMM (2-operand, measured 66.6us) --
__device__ __forceinline__ uint32_t smem_u32(const void* p) {
    return (uint32_t)__cvta_generic_to_shared(p);
}

__device__ __forceinline__ void ldsm_x4(uint32_t (&r)[4], uint32_t addr) {
    asm volatile("ldmatrix.sync.aligned.m8n8.x4.shared.b16 {%0,%1,%2,%3}, [%4];"
                 : "=r"(r[0]), "=r"(r[1]), "=r"(r[2]), "=r"(r[3]) : "r"(addr));
}

__device__ __forceinline__ void mma_f16(float (&d)[4], const uint32_t (&a)[4],
                                        uint32_t b0, uint32_t b1) {
    asm volatile(
        "mma.sync.aligned.m16n8k16.row.col.f32.f16.f16.f32 "
        "{%0,%1,%2,%3}, {%4,%5,%6,%7}, {%8,%9}, {%0,%1,%2,%3};"
        : "+f"(d[0]), "+f"(d[1]), "+f"(d[2]), "+f"(d[3])
        : "r"(a[0]), "r"(a[1]), "r"(a[2]), "r"(a[3]), "r"(b0), "r"(b1));
}

__device__ __forceinline__ void cp_async16(uint32_t dst, const void* src) {
    asm volatile("cp.async.ca.shared.global [%0], [%1], 16;" :: "r"(dst), "l"(src));
}

__global__ __launch_bounds__(256, 2)
void smoe_gemm_f16(float* __restrict__ out) {
    extern __shared__ __half smh[];
    __half* As = smh;                   // [2][BUFSZH]
    __half* Bs = smh + 2 * BUFSZH;      // [2][BUFSZH]

    const int b = blockIdx.z;
    const int nBlk = blockIdx.x * BN;
    const int mBlk = blockIdx.y * BM;

    const int tid = threadIdx.x;
    const int lane = tid & 31;
    const int wid = tid >> 5;
    const int warpM = wid >> 2;      // 0..1 -> 64-row slab
    const int warpN = wid & 3;       // 0..3 -> 32-col slab

    const __half* gA = g_xh  + (size_t)b * SS * DD + (size_t)mBlk * DD;
    const __half* gB = g_wch + (size_t)b * OO * DD + (size_t)nBlk * DD;

    const int aRow = (lane & 7) + ((lane >> 3) & 1) * 8;
    const int aK   = ((lane >> 4) & 1) * 8;
    int aOff[4];
#pragma unroll
    for (int mf = 0; mf < 4; mf++)
        aOff[mf] = (warpM * 64 + mf * 16 + aRow) * LDAH + aK;

    const int bRow = (lane & 7) + ((lane >> 4) & 1) * 8;
    const int bK   = ((lane >> 3) & 1) * 8;
    int bOff[2];
#pragma unroll
    for (int p = 0; p < 2; p++)
        bOff[p] = (warpN * 32 + p * 16 + bRow) * LDAH + bK;

    float acc[4][4][4];
#pragma unroll
    for (int i = 0; i < 4; i++)
#pragma unroll
        for (int j = 0; j < 4; j++)
#pragma unroll
            for (int k = 0; k < 4; k++) acc[i][j][k] = 0.f;

    auto issue = [&](int chunk, int buf) {
        const int kt = chunk * BKH;
#pragma unroll
        for (int p = 0; p < 4; p++) {
            int c = tid + p * 256;
            int row = c >> 3;
            int q8 = (c & 7) * 8;
            int so = buf * BUFSZH + row * LDAH + q8;
            size_t go = (size_t)row * DD + kt + q8;
            cp_async16(smem_u32(As + so), gA + go);
            cp_async16(smem_u32(Bs + so), gB + go);
        }
        asm volatile("cp.async.commit_group;");
    };

    issue(0, 0);

#pragma unroll 1
    for (int c = 0; c < KCHH; c++) {
        const int buf = c & 1;
        if (c + 1 < KCHH) {
            issue(c + 1, buf ^ 1);
            asm volatile("cp.async.wait_group 1;");
        } else {
            asm volatile("cp.async.wait_group 0;");
        }
        __syncthreads();

        const int bo = buf * BUFSZH;
#pragma unroll
        for (int kk = 0; kk < BKH; kk += 16) {
            uint32_t a[4][4];
#pragma unroll
            for (int mf = 0; mf < 4; mf++)
                ldsm_x4(a[mf], smem_u32(As + bo + aOff[mf] + kk));

#pragma unroll
            for (int p = 0; p < 2; p++) {
                uint32_t w[4];
                ldsm_x4(w, smem_u32(Bs + bo + bOff[p] + kk));
#pragma unroll
                for (int mf = 0; mf < 4; mf++) {
                    mma_f16(acc[mf][2 * p + 0], a[mf], w[0], w[1]);
                    mma_f16(acc[mf][2 * p + 1], a[mf], w[2], w[3]);
                }
            }
        }
        __syncthreads();
    }

    float2 bb[4];
#pragma unroll
    for (int nf = 0; nf < 4; nf++) {
        int n = nBlk + warpN * 32 + nf * 8 + (lane & 3) * 2;
        bb[nf].x = g_bias_c[b * OO + n];
        bb[nf].y = g_bias_c[b * OO + n + 1];
    }

    float* C = out + (size_t)b * SS * OO;
#pragma unroll
    for (int mf = 0; mf < 4; mf++) {
        int m = mBlk + warpM * 64 + mf * 16 + (lane >> 2);
#pragma unroll
        for (int nf = 0; nf < 4; nf++) {
            int n = nBlk + warpN * 32 + nf * 8 + (lane & 3) * 2;
            float2 v0, v1;
            v0.x = acc[mf][nf][0] + bb[nf].x;
            v0.y = acc[mf][nf][1] + bb[nf].y;
            v1.x = acc[mf][nf][2] + bb[nf].x;
            v1.y = acc[mf][nf][3] + bb[nf].y;
            *(float2*)(C + (size_t)m * OO + n) = v0;
            *(float2*)(C + (size_t)(m + 8) * OO + n) = v1;
        }
    }
}

// ---------------- launch ------------------------------------------------------
extern "C" void kernel_launch(void* const* d_in, const int* in_sizes, int n_in,
                              void* d_out, int out_size) {
    const float* x      = (const float*)d_in[0];  // (32,512,768)
    const float* w_gate = (const float*)d_in[1];  // (768,8)
    const float* weight = (const float*)d_in[2];  // (8,768,768)
    const float* bias   = (const float*)d_in[3];  // (8,768)
    float* out = (float*)d_out;
    float* loss_out = out + (out_size - 1);

    const int smem_bytes = 4 * BUFSZH * 2;  // 73728 B (A/B double-buffered, fp16)
    cudaFuncSetAttribute(smoe_gemm_f16,
                         cudaFuncAttributeMaxDynamicSharedMemorySize, smem_bytes);

    smoe_pool_kernel<<<dim3(BB, SCH, DD / 256), 256>>>(x);
    smoe_gate_kernel<<<1, 256>>>(w_gate, bias, loss_out);
    smoe_combine_kernel<<<OO * DD / 8 / 256, 256>>>(weight);
    smoe_gemm_f16<<<dim3(OO / BN, SS / BM, BB), 256, smem_bytes>>>(out);
}

// round 17
// speedup vs baseline: 1.2696x; 1.1925x over previous
#include <cuda_runtime.h>
#include <cuda_fp16.h>
#include <cstdint>

#define BB 32
#define SS 512
#define DD 768
#define OO 768
#define EE 8
#define SCH 16                     // pool s-chunks (32 rows each)

// fp16 GEMM tiling
#define BM 128
#define BN 128
#define BKH 64                     // 64 halfs = 128B rows
#define KCHH (DD / BKH)            // 12 k-chunks
#define LDAH 72                    // padded row stride (halfs) -> conflict-free ldmatrix
#define BUFSZH (128 * LDAH)        // halfs per tile buffer

// ---------------- scratch (device globals; no allocation allowed) ----------
__device__ float  g_pool_part[SCH * BB * DD];
__device__ float  g_gate_val[BB * 2];
__device__ int    g_gate_idx[BB * 2];
__device__ __half g_xh[(size_t)BB * SS * DD];   // 25.2MB fp16 copy of x
__device__ __half g_wch[(size_t)BB * OO * DD];  // 37.7MB combined expert weights (fp16)
__device__ float  g_bias_c[BB * OO];

// ---------------- kernel 1: pool v2 — float4 loads, vectorized fp16 stores ---
// grid (BB, SCH) = 512 CTAs, 192 threads; thread owns 4 consecutive d's.
__global__ __launch_bounds__(192)
void smoe_pool_kernel(const float* __restrict__ x) {
    const int b = blockIdx.x;
    const int sc = blockIdx.y;
    const int d = threadIdx.x * 4;
    const size_t base = (size_t)b * SS * DD + (size_t)sc * (SS / SCH) * DD + d;
    const float* xp = x + base;
    __half* xh = g_xh + base;

    float4 sum = make_float4(0.f, 0.f, 0.f, 0.f);
#pragma unroll 8
    for (int r = 0; r < SS / SCH; r++) {
        float4 v = *(const float4*)(xp + (size_t)r * DD);
        sum.x += v.x; sum.y += v.y; sum.z += v.z; sum.w += v.w;
        __half2 h0 = __floats2half2_rn(v.x, v.y);
        __half2 h1 = __floats2half2_rn(v.z, v.w);
        uint2 st;
        st.x = *(uint32_t*)&h0; st.y = *(uint32_t*)&h1;
        *(uint2*)(xh + (size_t)r * DD) = st;
    }
    *(float4*)(g_pool_part + (size_t)(sc * BB + b) * DD + d) = sum;
}

// ---------------- kernel 2: gate v2 — transposed w_gate, float4 reads --------
__device__ __forceinline__ float cv_squared8(const float* v) {
    float m = 0.f;
#pragma unroll
    for (int e = 0; e < EE; e++) m += v[e];
    m *= (1.0f / EE);
    float var = 0.f;
#pragma unroll
    for (int e = 0; e < EE; e++) { float dv = v[e] - m; var += dv * dv; }
    var *= (1.0f / (EE - 1));
    return var / (m * m + 1e-10f);
}

__global__ void smoe_gate_kernel(const float* __restrict__ w_gate,
                                 const float* __restrict__ bias,
                                 float* __restrict__ loss_out) {
    __shared__ float s_wgT[EE][DD];          // transposed: [e][d], 24 KB
    __shared__ float s_logits[BB][EE];
    __shared__ float s_gates[BB][EE];
    __shared__ float s_gv[BB][2];
    __shared__ int   s_gi[BB][2];

    const int tid = threadIdx.x;             // 256 threads
    const int lane = tid & 31;
    const int warp = tid >> 5;               // 8 warps; warp owns 4 batches

    for (int i = tid; i < DD * EE; i += 256) {
        int d = i >> 3, e = i & 7;
        s_wgT[e][d] = w_gate[i];
    }
    __syncthreads();

#pragma unroll
    for (int bi = 0; bi < 4; bi++) {
        const int b = warp * 4 + bi;
        float le[EE];
#pragma unroll
        for (int e = 0; e < EE; e++) le[e] = 0.f;

        for (int d4 = lane; d4 < DD / 4; d4 += 32) {   // float4 granularity
            float4 pv = make_float4(0.f, 0.f, 0.f, 0.f);
#pragma unroll
            for (int s = 0; s < SCH; s++) {
                float4 p = *(const float4*)(g_pool_part
                             + (size_t)(s * BB + b) * DD + d4 * 4);
                pv.x += p.x; pv.y += p.y; pv.z += p.z; pv.w += p.w;
            }
            pv.x *= (1.0f / SS); pv.y *= (1.0f / SS);
            pv.z *= (1.0f / SS); pv.w *= (1.0f / SS);
            const int d = d4 * 4;
#pragma unroll
            for (int e = 0; e < EE; e++) {
                le[e] += pv.x * s_wgT[e][d + 0] + pv.y * s_wgT[e][d + 1]
                       + pv.z * s_wgT[e][d + 2] + pv.w * s_wgT[e][d + 3];
            }
        }
#pragma unroll
        for (int e = 0; e < EE; e++) {
#pragma unroll
            for (int off = 16; off; off >>= 1)
                le[e] += __shfl_xor_sync(0xffffffffu, le[e], off);
        }
        if (lane < EE) s_logits[b][lane] = le[lane];
    }
    __syncthreads();

    if (tid < BB) {
        const int b = tid;
        float logits[EE];
#pragma unroll
        for (int e = 0; e < EE; e++) logits[e] = s_logits[b][e];

        int i1 = 0; float v1 = logits[0];
#pragma unroll
        for (int e = 1; e < EE; e++) if (logits[e] > v1) { v1 = logits[e]; i1 = e; }
        int i2 = -1; float v2 = -1e30f;
#pragma unroll
        for (int e = 0; e < EE; e++)
            if (e != i1 && logits[e] > v2) { v2 = logits[e]; i2 = e; }

        float ex = expf(v2 - v1);
        float inv = 1.0f / (1.0f + ex);
        float gtop = inv, gsec = ex * inv;

#pragma unroll
        for (int e = 0; e < EE; e++) s_gates[b][e] = 0.f;
        s_gates[b][i1] = gtop;
        s_gates[b][i2] = gsec;
        s_gv[b][0] = gtop; s_gv[b][1] = gsec;
        s_gi[b][0] = i1;   s_gi[b][1] = i2;

        g_gate_idx[b * 2 + 0] = i1;
        g_gate_idx[b * 2 + 1] = i2;
        g_gate_val[b * 2 + 0] = gtop;
        g_gate_val[b * 2 + 1] = gsec;
    }
    __syncthreads();

    // combined bias (float4): g_bias_c[b][n] = g0*bias[e0][n] + g1*bias[e1][n]
    for (int i = tid; i < BB * OO / 4; i += 256) {
        int b = i / (OO / 4), n4 = i - b * (OO / 4);
        float4 x0 = *(const float4*)(bias + (size_t)s_gi[b][0] * OO + n4 * 4);
        float4 x1 = *(const float4*)(bias + (size_t)s_gi[b][1] * OO + n4 * 4);
        float g0 = s_gv[b][0], g1 = s_gv[b][1];
        float4 r;
        r.x = g0 * x0.x + g1 * x1.x; r.y = g0 * x0.y + g1 * x1.y;
        r.z = g0 * x0.z + g1 * x1.z; r.w = g0 * x0.w + g1 * x1.w;
        *(float4*)(g_bias_c + (size_t)b * OO + n4 * 4) = r;
    }

    if (tid == 0) {
        float imp[EE], ldv[EE];
#pragma unroll
        for (int e = 0; e < EE; e++) {
            float s = 0.f, c = 0.f;
            for (int bi = 0; bi < BB; bi++) {
                float g = s_gates[bi][e];
                s += g;
                if (g > 0.f) c += 1.f;
            }
            imp[e] = s; ldv[e] = c;
        }
        loss_out[0] = (cv_squared8(imp) + cv_squared8(ldv)) * 0.01f;
    }
}

// ---------------- kernel 2.5: combine v3 — dense gates (measured ~6us) -------
__global__ __launch_bounds__(256)
void smoe_combine_kernel(const float* __restrict__ weight) {
    __shared__ float s_gd[BB][EE];           // dense gate matrix
    {
        const int t = threadIdx.x;           // 256 = BB*EE exactly
        s_gd[t >> 3][t & 7] = 0.f;
        __syncthreads();
        if (t < BB) {
            s_gd[t][g_gate_idx[2 * t + 0]] = g_gate_val[2 * t + 0];
            s_gd[t][g_gate_idx[2 * t + 1]] = g_gate_val[2 * t + 1];
        }
        __syncthreads();
    }

    const size_t i = (size_t)blockIdx.x * 256 + threadIdx.x; // 8-elem chunk id
    const float4* w4 = (const float4*)weight;

    float4 w[EE][2];                          // compile-time indexed only
#pragma unroll
    for (int e = 0; e < EE; e++) {
        size_t base = (size_t)e * (OO * DD / 4) + 2 * i;
        w[e][0] = w4[base];
        w[e][1] = w4[base + 1];
    }

#pragma unroll 4
    for (int b = 0; b < BB; b++) {
        float4 r0 = make_float4(0.f, 0.f, 0.f, 0.f);
        float4 r1 = make_float4(0.f, 0.f, 0.f, 0.f);
#pragma unroll
        for (int e = 0; e < EE; e++) {
            float g = s_gd[b][e];             // warp-uniform
            if (g != 0.f) {
                r0.x += g * w[e][0].x; r0.y += g * w[e][0].y;
                r0.z += g * w[e][0].z; r0.w += g * w[e][0].w;
                r1.x += g * w[e][1].x; r1.y += g * w[e][1].y;
                r1.z += g * w[e][1].z; r1.w += g * w[e][1].w;
            }
        }
        __half2 h0 = __floats2half2_rn(r0.x, r0.y);
        __half2 h1 = __floats2half2_rn(r0.z, r0.w);
        __half2 h2 = __floats2half2_rn(r1.x, r1.y);
        __half2 h3 = __floats2half2_rn(r1.z, r1.w);
        uint4 r;
        r.x = *(uint32_t*)&h0; r.y = *(uint32_t*)&h1;
        r.z = *(uint32_t*)&h2; r.w = *(uint32_t*)&h3;
        *(uint4*)(g_wch + (size_t)b * OO * DD + i * 8) = r;
    }
}

// ---------------- kernel 3: FP16 mma.sync GEMM (2-operand, measured 67us) ----
__device__ __forceinline__ uint32_t smem_u32(const void* p) {
    return (uint32_t)__cvta_generic_to_shared(p);
}

__device__ __forceinline__ void ldsm_x4(uint32_t (&r)[4], uint32_t addr) {
    asm volatile("ldmatrix.sync.aligned.m8n8.x4.shared.b16 {%0,%1,%2,%3}, [%4];"
                 : "=r"(r[0]), "=r"(r[1]), "=r"(r[2]), "=r"(r[3]) : "r"(addr));
}

__device__ __forceinline__ void mma_f16(float (&d)[4], const uint32_t (&a)[4],
                                        uint32_t b0, uint32_t b1) {
    asm volatile(
        "mma.sync.aligned.m16n8k16.row.col.f32.f16.f16.f32 "
        "{%0,%1,%2,%3}, {%4,%5,%6,%7}, {%8,%9}, {%0,%1,%2,%3};"
        : "+f"(d[0]), "+f"(d[1]), "+f"(d[2]), "+f"(d[3])
        : "r"(a[0]), "r"(a[1]), "r"(a[2]), "r"(a[3]), "r"(b0), "r"(b1));
}

__device__ __forceinline__ void cp_async16(uint32_t dst, const void* src) {
    asm volatile("cp.async.ca.shared.global [%0], [%1], 16;" :: "r"(dst), "l"(src));
}

__global__ __launch_bounds__(256, 2)
void smoe_gemm_f16(float* __restrict__ out) {
    extern __shared__ __half smh[];
    __half* As = smh;                   // [2][BUFSZH]
    __half* Bs = smh + 2 * BUFSZH;      // [2][BUFSZH]

    const int b = blockIdx.z;
    const int nBlk = blockIdx.x * BN;
    const int mBlk = blockIdx.y * BM;

    const int tid = threadIdx.x;
    const int lane = tid & 31;
    const int wid = tid >> 5;
    const int warpM = wid >> 2;      // 0..1 -> 64-row slab
    const int warpN = wid & 3;       // 0..3 -> 32-col slab

    const __half* gA = g_xh  + (size_t)b * SS * DD + (size_t)mBlk * DD;
    const __half* gB = g_wch + (size_t)b * OO * DD + (size_t)nBlk * DD;

    const int aRow = (lane & 7) + ((lane >> 3) & 1) * 8;
    const int aK   = ((lane >> 4) & 1) * 8;
    int aOff[4];
#pragma unroll
    for (int mf = 0; mf < 4; mf++)
        aOff[mf] = (warpM * 64 + mf * 16 + aRow) * LDAH + aK;

    const int bRow = (lane & 7) + ((lane >> 4) & 1) * 8;
    const int bK   = ((lane >> 3) & 1) * 8;
    int bOff[2];
#pragma unroll
    for (int p = 0; p < 2; p++)
        bOff[p] = (warpN * 32 + p * 16 + bRow) * LDAH + bK;

    float acc[4][4][4];
#pragma unroll
    for (int i = 0; i < 4; i++)
#pragma unroll
        for (int j = 0; j < 4; j++)
#pragma unroll
            for (int k = 0; k < 4; k++) acc[i][j][k] = 0.f;

    auto issue = [&](int chunk, int buf) {
        const int kt = chunk * BKH;
#pragma unroll
        for (int p = 0; p < 4; p++) {
            int c = tid + p * 256;
            int row = c >> 3;
            int q8 = (c & 7) * 8;
            int so = buf * BUFSZH + row * LDAH + q8;
            size_t go = (size_t)row * DD + kt + q8;
            cp_async16(smem_u32(As + so), gA + go);
            cp_async16(smem_u32(Bs + so), gB + go);
        }
        asm volatile("cp.async.commit_group;");
    };

    issue(0, 0);

#pragma unroll 1
    for (int c = 0; c < KCHH; c++) {
        const int buf = c & 1;
        if (c + 1 < KCHH) {
            issue(c + 1, buf ^ 1);
            asm volatile("cp.async.wait_group 1;");
        } else {
            asm volatile("cp.async.wait_group 0;");
        }
        __syncthreads();

        const int bo = buf * BUFSZH;
#pragma unroll
        for (int kk = 0; kk < BKH; kk += 16) {
            uint32_t a[4][4];
#pragma unroll
            for (int mf = 0; mf < 4; mf++)
                ldsm_x4(a[mf], smem_u32(As + bo + aOff[mf] + kk));

#pragma unroll
            for (int p = 0; p < 2; p++) {
                uint32_t w[4];
                ldsm_x4(w, smem_u32(Bs + bo + bOff[p] + kk));
#pragma unroll
                for (int mf = 0; mf < 4; mf++) {
                    mma_f16(acc[mf][2 * p + 0], a[mf], w[0], w[1]);
                    mma_f16(acc[mf][2 * p + 1], a[mf], w[2], w[3]);
                }
            }
        }
        __syncthreads();
    }

    float2 bb[4];
#pragma unroll
    for (int nf = 0; nf < 4; nf++) {
        int n = nBlk + warpN * 32 + nf * 8 + (lane & 3) * 2;
        bb[nf].x = g_bias_c[b * OO + n];
        bb[nf].y = g_bias_c[b * OO + n + 1];
    }

    float* C = out + (size_t)b * SS * OO;
#pragma unroll
    for (int mf = 0; mf < 4; mf++) {
        int m = mBlk + warpM * 64 + mf * 16 + (lane >> 2);
#pragma unroll
        for (int nf = 0; nf < 4; nf++) {
            int n = nBlk + warpN * 32 + nf * 8 + (lane & 3) * 2;
            float2 v0, v1;
            v0.x = acc[mf][nf][0] + bb[nf].x;
            v0.y = acc[mf][nf][1] + bb[nf].y;
            v1.x = acc[mf][nf][2] + bb[nf].x;
            v1.y = acc[mf][nf][3] + bb[nf].y;
            *(float2*)(C + (size_t)m * OO + n) = v0;
            *(float2*)(C + (size_t)(m + 8) * OO + n) = v1;
        }
    }
}

// ---------------- launch ------------------------------------------------------
extern "C" void kernel_launch(void* const* d_in, const int* in_sizes, int n_in,
                              void* d_out, int out_size) {
    const float* x      = (const float*)d_in[0];  // (32,512,768)
    const float* w_gate = (const float*)d_in[1];  // (768,8)
    const float* weight = (const float*)d_in[2];  // (8,768,768)
    const float* bias   = (const float*)d_in[3];  // (8,768)
    float* out = (float*)d_out;
    float* loss_out = out + (out_size - 1);

    const int smem_bytes = 4 * BUFSZH * 2;  // 73728 B (A/B double-buffered, fp16)
    cudaFuncSetAttribute(smoe_gemm_f16,
                         cudaFuncAttributeMaxDynamicSharedMemorySize, smem_bytes);

    smoe_pool_kernel<<<dim3(BB, SCH), 192>>>(x);
    smoe_gate_kernel<<<1, 256>>>(w_gate, bias, loss_out);
    smoe_combine_kernel<<<OO * DD / 8 / 256, 256>>>(weight);
    smoe_gemm_f16<<<dim3(OO / BN, SS / BM, BB), 256, smem_bytes>>>(out);
}